// round 9
// baseline (speedup 1.0000x reference)
#include <cuda_runtime.h>
#include <cstdint>

// NaiveFourierKANLayer via mma.sync tf32 (sm_103 portable HMMA path).
// y[b,j] = sum_{i,k} cos(x[b,i]k)C0[j,i,k] + sin(x[b,i]k)C1[j,i,k] + bias[j]
// GEMM: M=2048(b), N=256(j), K=(i,plane,k)=153600 (k padded 300->304).
// This round: occupancy-2 (BN=128, 97KB smem, <=128 regs) so two CTAs/SM
// interleave: one CTA's feature-generation hides under the other's HMMAs.

#define NT     256
#define BMT    128          // CTA M tile
#define BNT    128          // CTA N tile
#define ID     256
#define JD     256
#define KG     300
#define SPLIT  8
#define I_PER  32           // i's per CTA
#define KCPI   19           // 16-angle chunks per i (19*16 = 304)
#define STAGES (I_PER * KCPI)   // 608

#define CTRL   1024
#define A_SZ   16384        // 128 rows x 128B  ([cos16|sin16] tf32)
#define B_SZ   16384        // 128 rows x 128B  ([C0 k16 | C1 k16] tf32)
#define STG    (A_SZ + B_SZ)
#define SMEM_TOTAL (CTRL + 3 * STG)   // 99328 -> 2 CTAs/SM fit in 227KB

// tf32-RNA-rounded, SW128-pre-swizzled coeff tiles, k padded to 304:
// tile ((i*19+kc)*2+jh): [128 j rows][8 chunks 16B], chunk c<4 = C0, c>=4 = C1.
__device__ __align__(128) float g_B[(size_t)ID * KCPI * 2 * 128 * 32];

__device__ __forceinline__ uint32_t s2u(const void* p) {
    uint32_t a;
    asm("{ .reg .u64 t; cvta.to.shared.u64 t, %1; cvt.u32.u64 %0, t; }" : "=r"(a) : "l"(p));
    return a;
}
__device__ __forceinline__ float tf32rn(float x) {
    uint32_t o; asm("cvt.rna.satfinite.tf32.f32 %0, %1;" : "=r"(o) : "f"(x));
    return __uint_as_float(o);
}

#define MBAR_INIT(a, c) asm volatile("mbarrier.init.shared.b64 [%0], %1;" :: "r"(a), "r"(c) : "memory")
#define MBAR_ARRIVE(a)  asm volatile("mbarrier.arrive.shared.b64 _, [%0];" :: "r"(a) : "memory")
#define MBAR_EXPECT_TX(a, b) \
    asm volatile("mbarrier.arrive.expect_tx.shared.b64 _, [%0], %1;" :: "r"(a), "r"(b) : "memory")
#define MBAR_WAIT(a, ph)                                                              \
    asm volatile("{\n\t.reg .pred P;\n\t"                                             \
        "WL_%=:\n\t"                                                                  \
        "mbarrier.try_wait.parity.acquire.cta.shared::cta.b64 P, [%0], %1, 0x989680;\n\t" \
        "@P bra.uni WD_%=;\n\t"                                                       \
        "bra.uni WL_%=;\n\t"                                                          \
        "WD_%=:\n\t}" :: "r"(a), "r"(ph) : "memory")

#define LDSM4(R, addr)                                                                \
    asm volatile("ldmatrix.sync.aligned.m8n8.x4.shared.b16 {%0,%1,%2,%3}, [%4];"      \
        : "=r"((R)[0]), "=r"((R)[1]), "=r"((R)[2]), "=r"((R)[3]) : "r"(addr))

__device__ __forceinline__ void mma8(float* d, const uint32_t* a, const uint32_t* b) {
    asm volatile("mma.sync.aligned.m16n8k8.row.col.f32.tf32.tf32.f32 "
        "{%0,%1,%2,%3}, {%4,%5,%6,%7}, {%8,%9}, {%0,%1,%2,%3};"
        : "+f"(d[0]), "+f"(d[1]), "+f"(d[2]), "+f"(d[3])
        : "r"(a[0]), "r"(a[1]), "r"(a[2]), "r"(a[3]), "r"(b[0]), "r"(b[1]));
}

// ---------------------------------------------------------------------------
__global__ void __launch_bounds__(NT)
fkan_init(float* __restrict__ out, const float* __restrict__ bias, int n) {
    int t = blockIdx.x * blockDim.x + threadIdx.x;
    if (t < n) out[t] = bias[t & (JD - 1)];
}

// coeffs[d][j][i][k] -> g_B, tf32 RNA-rounded, SW128-swizzled, k padded.
__global__ void __launch_bounds__(NT)
fkan_pre(const float* __restrict__ co) {
    size_t lin = (size_t)blockIdx.x * NT + threadIdx.x;   // (tile*128+jr)*8+c
    if (lin >= (size_t)ID * KCPI * 2 * 128 * 8) return;
    int c    = (int)(lin & 7);
    int jr   = (int)((lin >> 3) & 127);
    int tile = (int)(lin >> 10);
    int jh   = tile & 1;
    int kc   = (tile >> 1) % KCPI;
    int i    = (tile >> 1) / KCPI;
    int d    = c >> 2;
    int k    = kc * 16 + (c & 3) * 4;
    int j    = jh * 128 + jr;

    float4 v = make_float4(0.f, 0.f, 0.f, 0.f);
    if (k < KG) {   // k <= 296 here -> float4 stays inside the 300-long row
        v = *(const float4*)(co + ((size_t)(d * JD + j) * ID + i) * KG + k);
        v.x = tf32rn(v.x); v.y = tf32rn(v.y); v.z = tf32rn(v.z); v.w = tf32rn(v.w);
    }
    uint32_t off = (uint32_t)jr * 128 + (((uint32_t)c ^ (uint32_t)(jr & 7)) << 4);
    *(float4*)((char*)g_B + (size_t)tile * 16384 + off) = v;
}

// ---------------------------------------------------------------------------
struct PState { float xv, c2, s2; };

__device__ __forceinline__ void produce(int u, uint32_t sb, char* smem,
                                        const char* btile_base, const float* xp,
                                        int t, int r, int h, PState& P)
{
    const int slot = u % 3;
    const int kc   = u % KCPI;
    const int il   = u / KCPI;
    const uint32_t mF = sb + (uint32_t)slot * 8u;

    if (t == 0) {   // B: one 16KB pre-swizzled bulk copy
        const char* src = btile_base + (size_t)(il * KCPI + kc) * 2 * 16384;
        MBAR_EXPECT_TX(mF, (uint32_t)B_SZ);
        asm volatile("cp.async.bulk.shared::cluster.global.mbarrier::complete_tx::bytes "
                     "[%0], [%1], %2, [%3];"
                     :: "r"(sb + CTRL + slot * STG + A_SZ), "l"(src),
                        "r"((uint32_t)B_SZ), "r"(mF) : "memory");
    }

    if (kc == 0) { P.xv = xp[il]; __sincosf(P.xv + P.xv, &P.s2, &P.c2); }

    // 16 angles k = kc*16 + {1..16}: 2 MUFU seeds + rotations by 2x.
    const float k0f = (float)(kc * 16 + 1);
    float s0, c0, s1, c1;
    __sincosf(P.xv * k0f,         &s0, &c0);   // fp32 x*k matches reference rounding
    __sincosf(P.xv * (k0f + 1.f), &s1, &c1);

    char* Arow = smem + CTRL + slot * STG + r * 128;
    const uint32_t msk = (uint32_t)(r & 7);
    #pragma unroll
    for (int q = 0; q < 4; q++) {
        float v0 = h ? s0 : c0;
        float v1 = h ? s1 : c1;
        float nc0 = c0 * P.c2 - s0 * P.s2, ns0 = s0 * P.c2 + c0 * P.s2;
        float nc1 = c1 * P.c2 - s1 * P.s2, ns1 = s1 * P.c2 + c1 * P.s2;
        float v2 = h ? ns0 : nc0;
        float v3 = h ? ns1 : nc1;
        c0 = nc0 * P.c2 - ns0 * P.s2;  s0 = ns0 * P.c2 + nc0 * P.s2;
        c1 = nc1 * P.c2 - ns1 * P.s2;  s1 = ns1 * P.c2 + nc1 * P.s2;
        float4 w;
        w.x = tf32rn(v0); w.y = tf32rn(v1); w.z = tf32rn(v2); w.w = tf32rn(v3);
        if (kc == KCPI - 1 && q == 3) w = make_float4(0.f, 0.f, 0.f, 0.f);  // k > 300
        *(float4*)(Arow + ((((uint32_t)(h * 4 + q)) ^ msk) << 4)) = w;
    }
    MBAR_ARRIVE(mF);   // release: A stores visible to full-waiters
}

__global__ void __launch_bounds__(NT, 2)
fkan_gemm(const float* __restrict__ x, float* __restrict__ out)
{
    extern __shared__ char smem[];
    const uint32_t sb = s2u(smem);
    const int t = threadIdx.x, lane = t & 31, wid = t >> 5;
    const int b0    = blockIdx.x * BMT;
    const int jh    = blockIdx.y;          // j-half: j0 = jh*128
    const int ibase = blockIdx.z * I_PER;

    if (t == 0) { MBAR_INIT(sb, 257); MBAR_INIT(sb + 8, 257); MBAR_INIT(sb + 16, 257); }
    __syncthreads();

    // producer ids: r = m-row, h = plane (0=cos chunks 0-3, 1=sin chunks 4-7)
    const int r = t & 127, h = t >> 7;
    const float* xp = x + (size_t)(b0 + r) * ID + ibase;
    const char* btile_base = (const char*)g_B +
        ((size_t)(ibase * KCPI) * 2 + jh) * 16384;
    PState P;

    // consumer: 8 warps as 2(m) x 4(n), warp tile 64x32
    const int wm = wid >> 2, wn = wid & 3;
    const int mbase = wm * 64, nbase = wn * 32;
    const uint32_t msk = (uint32_t)(lane & 7);
    const int a_rl = ((lane >> 3) & 1) * 8 + (lane & 7);
    const uint32_t akh = (uint32_t)(lane >> 4);
    const int b_rl = ((lane >> 4) << 3) + (lane & 7);
    const uint32_t bkh = (uint32_t)((lane >> 3) & 1);
    uint32_t aoff[4], boff[2];
    #pragma unroll
    for (int mi = 0; mi < 4; mi++) aoff[mi] = (uint32_t)(mbase + mi * 16 + a_rl) * 128u;
    #pragma unroll
    for (int g = 0; g < 2; g++)   boff[g] = (uint32_t)(nbase + g * 16 + b_rl) * 128u;

    float acc[4][4][4];
    #pragma unroll
    for (int a = 0; a < 4; a++)
        #pragma unroll
        for (int b = 0; b < 4; b++)
            #pragma unroll
            for (int c = 0; c < 4; c++) acc[a][b][c] = 0.f;

    produce(0, sb, smem, btile_base, xp, t, r, h, P);
    produce(1, sb, smem, btile_base, xp, t, r, h, P);
    produce(2, sb, smem, btile_base, xp, t, r, h, P);

    for (int s = 0; s < STAGES; s++) {
        const int slot = s % 3;
        const uint32_t ph = (uint32_t)((s / 3) & 1);
        MBAR_WAIT(sb + (uint32_t)slot * 8u, ph);
        const uint32_t Ab = sb + CTRL + slot * STG;
        const uint32_t Bb = Ab + A_SZ;
        #pragma unroll
        for (int kq = 0; kq < 4; kq++) {
            uint32_t av[4][4], bv[2][4];
            const uint32_t ak = ((((uint32_t)(kq * 2) + akh) ^ msk) << 4);
            const uint32_t bk = ((((uint32_t)(kq * 2) + bkh) ^ msk) << 4);
            #pragma unroll
            for (int mi = 0; mi < 4; mi++) LDSM4(av[mi], Ab + aoff[mi] + ak);
            #pragma unroll
            for (int g = 0; g < 2; g++)   LDSM4(bv[g], Bb + boff[g] + bk);
            #pragma unroll
            for (int mi = 0; mi < 4; mi++)
                #pragma unroll
                for (int nt = 0; nt < 4; nt++)
                    mma8(acc[mi][nt], av[mi], &bv[nt >> 1][(nt & 1) * 2]);
        }
        if (s + 3 < STAGES) {
            __syncthreads();                      // all readers done with this slot
            produce(s + 3, sb, smem, btile_base, xp, t, r, h, P);
        }
    }

    // epilogue: split-K accumulate (out pre-initialized with bias)
    const int g4 = lane >> 2, t4 = lane & 3;
    #pragma unroll
    for (int mi = 0; mi < 4; mi++) {
        const int row = b0 + mbase + mi * 16 + g4;
        #pragma unroll
        for (int nt = 0; nt < 4; nt++) {
            const int col = jh * BNT + nbase + nt * 8 + t4 * 2;
            atomicAdd(out + (size_t)row * JD + col,           acc[mi][nt][0]);
            atomicAdd(out + (size_t)row * JD + col + 1,       acc[mi][nt][1]);
            atomicAdd(out + (size_t)(row + 8) * JD + col,     acc[mi][nt][2]);
            atomicAdd(out + (size_t)(row + 8) * JD + col + 1, acc[mi][nt][3]);
        }
    }
}

// ---------------------------------------------------------------------------
extern "C" void kernel_launch(void* const* d_in, const int* in_sizes, int n_in,
                              void* d_out, int out_size)
{
    const float* x    = (const float*)d_in[0];   // [2048, 256]
    const float* co   = (const float*)d_in[1];   // [2, 256, 256, 300]
    const float* bias = (const float*)d_in[2];   // [1, 256]
    float* out = (float*)d_out;                  // [2048, 256] fp32

    cudaFuncSetAttribute(fkan_gemm, cudaFuncAttributeMaxDynamicSharedMemorySize, SMEM_TOTAL);

    fkan_init<<<(out_size + NT - 1) / NT, NT>>>(out, bias, out_size);
    fkan_pre<<<(int)(((size_t)ID * KCPI * 2 * 128 * 8 + NT - 1) / NT), NT>>>(co);

    dim3 grid(2048 / BMT, JD / BNT, SPLIT);      // (16, 2, 8) = 256 CTAs, occ 2
    fkan_gemm<<<grid, NT, SMEM_TOTAL>>>(x, out);
}

// round 11
// speedup vs baseline: 1.0860x; 1.0860x over previous
#include <cuda_runtime.h>
#include <cstdint>

// NaiveFourierKANLayer via mma.sync tf32 (sm_103 portable HMMA path).
// y[b,j] = sum_{i,k} cos(x[b,i]k)C0[j,i,k] + sin(x[b,i]k)C1[j,i,k] + bias[j]
// GEMM: M=2048(b), N=256(j), K=(i,plane,k)=153600 (k padded 300->304).
// Round 10: back to BN=256 (R7 structure, best at 1060us) but 512 threads
// (16 warps = 4/SMSP) so produce/LDSM/sync latency hides behind HMMAs.

#define NT     512          // gemm threads
#define PTN    256          // helper-kernel threads
#define BMT    128          // CTA M tile
#define ID     256
#define JD     256
#define KG     300
#define SPLIT  8
#define I_PER  32           // i's per CTA
#define KCPI   19           // 16-angle chunks per i (19*16 = 304)
#define STAGES (I_PER * KCPI)   // 608

#define CTRL   1024
#define A_SZ   16384        // 128 rows x 128B  ([cos16|sin16] tf32)
#define B_SZ   32768        // 256 rows x 128B  ([C0 k16 | C1 k16] tf32)
#define STG    (A_SZ + B_SZ)
#define SMEM_TOTAL (CTRL + 3 * STG)   // 148480

// tf32-RNA-rounded, SW128-pre-swizzled coeff tiles, k padded to 304:
// tile (i*19+kc): [256 j rows][8 chunks of 16B], chunk c<4 = C0, c>=4 = C1.
__device__ __align__(128) float g_B[(size_t)ID * KCPI * JD * 32];

__device__ __forceinline__ uint32_t s2u(const void* p) {
    uint32_t a;
    asm("{ .reg .u64 t; cvta.to.shared.u64 t, %1; cvt.u32.u64 %0, t; }" : "=r"(a) : "l"(p));
    return a;
}
__device__ __forceinline__ float tf32rn(float x) {
    uint32_t o; asm("cvt.rna.satfinite.tf32.f32 %0, %1;" : "=r"(o) : "f"(x));
    return __uint_as_float(o);
}

#define MBAR_INIT(a, c) asm volatile("mbarrier.init.shared.b64 [%0], %1;" :: "r"(a), "r"(c) : "memory")
#define MBAR_ARRIVE(a)  asm volatile("mbarrier.arrive.shared.b64 _, [%0];" :: "r"(a) : "memory")
#define MBAR_EXPECT_TX(a, b) \
    asm volatile("mbarrier.arrive.expect_tx.shared.b64 _, [%0], %1;" :: "r"(a), "r"(b) : "memory")
#define MBAR_WAIT(a, ph)                                                              \
    asm volatile("{\n\t.reg .pred P;\n\t"                                             \
        "WL_%=:\n\t"                                                                  \
        "mbarrier.try_wait.parity.acquire.cta.shared::cta.b64 P, [%0], %1, 0x989680;\n\t" \
        "@P bra.uni WD_%=;\n\t"                                                       \
        "bra.uni WL_%=;\n\t"                                                          \
        "WD_%=:\n\t}" :: "r"(a), "r"(ph) : "memory")

#define LDSM4(R, addr)                                                                \
    asm volatile("ldmatrix.sync.aligned.m8n8.x4.shared.b16 {%0,%1,%2,%3}, [%4];"      \
        : "=r"((R)[0]), "=r"((R)[1]), "=r"((R)[2]), "=r"((R)[3]) : "r"(addr))

__device__ __forceinline__ void mma8(float* d, const uint32_t* a, const uint32_t* b) {
    asm volatile("mma.sync.aligned.m16n8k8.row.col.f32.tf32.tf32.f32 "
        "{%0,%1,%2,%3}, {%4,%5,%6,%7}, {%8,%9}, {%0,%1,%2,%3};"
        : "+f"(d[0]), "+f"(d[1]), "+f"(d[2]), "+f"(d[3])
        : "r"(a[0]), "r"(a[1]), "r"(a[2]), "r"(a[3]), "r"(b[0]), "r"(b[1]));
}

// ---------------------------------------------------------------------------
__global__ void __launch_bounds__(PTN)
fkan_init(float* __restrict__ out, const float* __restrict__ bias, int n) {
    int t = blockIdx.x * blockDim.x + threadIdx.x;
    if (t < n) out[t] = bias[t & (JD - 1)];
}

// coeffs[d][j][i][k] -> g_B, tf32 RNA-rounded, SW128-swizzled, k padded.
__global__ void __launch_bounds__(PTN)
fkan_pre(const float* __restrict__ co) {
    size_t lin = (size_t)blockIdx.x * PTN + threadIdx.x;   // ((i*19+kc)*256+j)*8+c
    if (lin >= (size_t)ID * KCPI * JD * 8) return;
    int c    = (int)(lin & 7);
    int j    = (int)((lin >> 3) & 255);
    int tile = (int)(lin >> 11);
    int kc   = tile % KCPI;
    int i    = tile / KCPI;
    int d    = c >> 2;
    int k    = kc * 16 + (c & 3) * 4;

    float4 v = make_float4(0.f, 0.f, 0.f, 0.f);
    if (k < KG) {  // k <= 296 -> float4 stays inside the 300-long row
        v = *(const float4*)(co + ((size_t)(d * JD + j) * ID + i) * KG + k);
        v.x = tf32rn(v.x); v.y = tf32rn(v.y); v.z = tf32rn(v.z); v.w = tf32rn(v.w);
    }
    uint32_t off = (uint32_t)j * 128 + (((uint32_t)c ^ (uint32_t)(j & 7)) << 4);
    *(float4*)((char*)g_B + (size_t)tile * 32768 + off) = v;
}

// ---------------------------------------------------------------------------
struct PState { float xv, c2, s2; };

// 512 producer threads: thread (r, h, qq) writes quads q = 2qq, 2qq+1
// (8 angles k = kc*16 + 8qq + {1..8}) of plane h for m-row r.
__device__ __forceinline__ void produce(int u, uint32_t sb, char* smem, int ibase,
                                        const float* xp, int t, int r, int h, int qq,
                                        PState& P)
{
    const int slot = u % 3;
    const int kc   = u % KCPI;
    const int il   = u / KCPI;
    const uint32_t mF = sb + (uint32_t)slot * 8u;

    if (t == 0) {   // B: one 32KB pre-swizzled bulk copy
        const char* src = (const char*)g_B + (size_t)((ibase + il) * KCPI + kc) * 32768;
        MBAR_EXPECT_TX(mF, (uint32_t)B_SZ);
        asm volatile("cp.async.bulk.shared::cluster.global.mbarrier::complete_tx::bytes "
                     "[%0], [%1], %2, [%3];"
                     :: "r"(sb + CTRL + slot * STG + A_SZ), "l"(src),
                        "r"((uint32_t)B_SZ), "r"(mF) : "memory");
    }

    if (kc == 0) { P.xv = xp[il]; __sincosf(P.xv + P.xv, &P.s2, &P.c2); }

    // seeds at k0, k0+1; rotate both chains by 2x per step
    const float k0f = (float)(kc * 16 + qq * 8 + 1);
    float s0, c0, s1, c1;
    __sincosf(P.xv * k0f,         &s0, &c0);   // fp32 x*k matches reference rounding
    __sincosf(P.xv * (k0f + 1.f), &s1, &c1);

    char* Arow = smem + CTRL + slot * STG + r * 128;
    const uint32_t msk = (uint32_t)(r & 7);
    #pragma unroll
    for (int q2 = 0; q2 < 2; q2++) {
        float v0 = h ? s0 : c0;
        float v1 = h ? s1 : c1;
        float nc0 = c0 * P.c2 - s0 * P.s2, ns0 = s0 * P.c2 + c0 * P.s2;
        float nc1 = c1 * P.c2 - s1 * P.s2, ns1 = s1 * P.c2 + c1 * P.s2;
        float v2 = h ? ns0 : nc0;
        float v3 = h ? ns1 : nc1;
        c0 = nc0 * P.c2 - ns0 * P.s2;  s0 = ns0 * P.c2 + nc0 * P.s2;
        c1 = nc1 * P.c2 - ns1 * P.s2;  s1 = ns1 * P.c2 + nc1 * P.s2;
        float4 w;
        w.x = tf32rn(v0); w.y = tf32rn(v1); w.z = tf32rn(v2); w.w = tf32rn(v3);
        if (kc == KCPI - 1 && qq == 1 && q2 == 1)       // k > 300
            w = make_float4(0.f, 0.f, 0.f, 0.f);
        const uint32_t chunk = (uint32_t)(h * 4 + qq * 2 + q2);
        *(float4*)(Arow + ((chunk ^ msk) << 4)) = w;
    }
    MBAR_ARRIVE(mF);   // release: A stores visible to full-waiters
}

__global__ void __launch_bounds__(NT, 1)
fkan_gemm(const float* __restrict__ x, float* __restrict__ out)
{
    extern __shared__ char smem[];
    const uint32_t sb = s2u(smem);
    const int t = threadIdx.x, lane = t & 31, wid = t >> 5;
    const int b0    = blockIdx.x * BMT;
    const int ibase = blockIdx.y * I_PER;

    if (t == 0) { MBAR_INIT(sb, NT + 1); MBAR_INIT(sb + 8, NT + 1); MBAR_INIT(sb + 16, NT + 1); }
    __syncthreads();

    // producer ids
    const int r = t & 127, h = (t >> 7) & 1, qq = t >> 8;
    const float* xp = x + (size_t)(b0 + r) * ID + ibase;
    PState P;

    // consumer: 16 warps as 4(m) x 4(n), warp tile 32x64
    const int wm = wid >> 2, wn = wid & 3;
    const int mbase = wm * 32, nbase = wn * 64;
    const uint32_t msk = (uint32_t)(lane & 7);
    const int a_rl = ((lane >> 3) & 1) * 8 + (lane & 7);   // ldmatrix A row-in-group
    const uint32_t akh = (uint32_t)(lane >> 4);            // A k-half
    const int b_rl = ((lane >> 4) << 3) + (lane & 7);      // ldmatrix B row-in-group
    const uint32_t bkh = (uint32_t)((lane >> 3) & 1);      // B k-half
    uint32_t aoff[2], boff[4];
    #pragma unroll
    for (int mi = 0; mi < 2; mi++) aoff[mi] = (uint32_t)(mbase + mi * 16 + a_rl) * 128u;
    #pragma unroll
    for (int g = 0; g < 4; g++)   boff[g] = (uint32_t)(nbase + g * 16 + b_rl) * 128u;

    float acc[2][8][4];
    #pragma unroll
    for (int a = 0; a < 2; a++)
        #pragma unroll
        for (int b = 0; b < 8; b++)
            #pragma unroll
            for (int c = 0; c < 4; c++) acc[a][b][c] = 0.f;

    produce(0, sb, smem, ibase, xp, t, r, h, qq, P);
    produce(1, sb, smem, ibase, xp, t, r, h, qq, P);
    produce(2, sb, smem, ibase, xp, t, r, h, qq, P);

    for (int s = 0; s < STAGES; s++) {
        const int slot = s % 3;
        const uint32_t ph = (uint32_t)((s / 3) & 1);
        MBAR_WAIT(sb + (uint32_t)slot * 8u, ph);
        const uint32_t Ab = sb + CTRL + slot * STG;
        const uint32_t Bb = Ab + A_SZ;
        #pragma unroll
        for (int kq = 0; kq < 4; kq++) {
            uint32_t av[2][4], bv[4][4];
            const uint32_t ak = ((((uint32_t)(kq * 2) + akh) ^ msk) << 4);
            const uint32_t bk = ((((uint32_t)(kq * 2) + bkh) ^ msk) << 4);
            #pragma unroll
            for (int mi = 0; mi < 2; mi++) LDSM4(av[mi], Ab + aoff[mi] + ak);
            #pragma unroll
            for (int g = 0; g < 4; g++)   LDSM4(bv[g], Bb + boff[g] + bk);
            #pragma unroll
            for (int mi = 0; mi < 2; mi++)
                #pragma unroll
                for (int nt = 0; nt < 8; nt++)
                    mma8(acc[mi][nt], av[mi], &bv[nt >> 1][(nt & 1) * 2]);
        }
        if (s + 3 < STAGES) {
            __syncthreads();                      // all readers done with this slot
            produce(s + 3, sb, smem, ibase, xp, t, r, h, qq, P);
        }
    }

    // epilogue: split-K accumulate (out pre-initialized with bias)
    const int g4 = lane >> 2, t4 = lane & 3;
    #pragma unroll
    for (int mi = 0; mi < 2; mi++) {
        const int row = b0 + mbase + mi * 16 + g4;
        #pragma unroll
        for (int nt = 0; nt < 8; nt++) {
            const int col = nbase + nt * 8 + t4 * 2;
            atomicAdd(out + (size_t)row * JD + col,           acc[mi][nt][0]);
            atomicAdd(out + (size_t)row * JD + col + 1,       acc[mi][nt][1]);
            atomicAdd(out + (size_t)(row + 8) * JD + col,     acc[mi][nt][2]);
            atomicAdd(out + (size_t)(row + 8) * JD + col + 1, acc[mi][nt][3]);
        }
    }
}

// ---------------------------------------------------------------------------
extern "C" void kernel_launch(void* const* d_in, const int* in_sizes, int n_in,
                              void* d_out, int out_size)
{
    const float* x    = (const float*)d_in[0];   // [2048, 256]
    const float* co   = (const float*)d_in[1];   // [2, 256, 256, 300]
    const float* bias = (const float*)d_in[2];   // [1, 256]
    float* out = (float*)d_out;                  // [2048, 256] fp32

    cudaFuncSetAttribute(fkan_gemm, cudaFuncAttributeMaxDynamicSharedMemorySize, SMEM_TOTAL);

    fkan_init<<<(out_size + PTN - 1) / PTN, PTN>>>(out, bias, out_size);
    fkan_pre<<<(int)(((size_t)ID * KCPI * JD * 8 + PTN - 1) / PTN), PTN>>>(co);

    dim3 grid(2048 / BMT, SPLIT);                // (16, 8) = 128 CTAs, one wave
    fkan_gemm<<<grid, NT, SMEM_TOTAL>>>(x, out);
}

// round 13
// speedup vs baseline: 1.8558x; 1.7089x over previous
#include <cuda_runtime.h>
#include <cuda_fp16.h>
#include <cstdint>

// NaiveFourierKANLayer via mma.sync fp16 m16n8k16 (sm_103 portable HMMA path).
// y[b,j] = sum_{i,k} cos(x[b,i]k)C0[j,i,k] + sin(x[b,i]k)C1[j,i,k] + bias[j]
// GEMM: M=2048(b), N=256(j), K=(i,plane,k)=153600 (k padded 300->320).
// fp16 has the same 11-bit mantissa as tf32 but 2x FLOP per HMMA instruction;
// accumulation is fp32 -> same accuracy, half the tensor-issue cycles.

#define NT     512          // gemm threads (16 warps, 4/SMSP)
#define PTN    256          // helper-kernel threads
#define BMT    128          // CTA M tile
#define ID     256
#define JD     256
#define KG     300
#define SPLIT  8
#define I_PER  32           // i's per CTA
#define KCPI   10           // 32-angle chunks per i (10*32 = 320)
#define STAGES (I_PER * KCPI)   // 320

#define CTRL   1024
#define A_SZ   16384        // 128 rows x 128B  ([cos32|sin32] fp16)
#define B_SZ   32768        // 256 rows x 128B  ([C0 k32 | C1 k32] fp16)
#define STG    (A_SZ + B_SZ)
#define SMEM_TOTAL (CTRL + 3 * STG)   // 148480

// fp16, SW128-pre-swizzled coeff tiles, k padded to 320:
// tile (i*10+kc): [256 j rows][8 chunks 16B=8 fp16], chunk c<4 = C0, c>=4 = C1.
__device__ __align__(128) uint32_t g_B[(size_t)ID * KCPI * JD * 32];   // 84 MB

__device__ __forceinline__ uint32_t s2u(const void* p) {
    uint32_t a;
    asm("{ .reg .u64 t; cvta.to.shared.u64 t, %1; cvt.u32.u64 %0, t; }" : "=r"(a) : "l"(p));
    return a;
}
// pack two fp32 -> fp16x2 (lo = first arg, hi = second arg), round-to-nearest
__device__ __forceinline__ uint32_t pack_h2(float lo, float hi) {
    uint32_t r;
    asm("cvt.rn.f16x2.f32 %0, %1, %2;" : "=r"(r) : "f"(hi), "f"(lo));
    return r;
}

#define MBAR_INIT(a, c) asm volatile("mbarrier.init.shared.b64 [%0], %1;" :: "r"(a), "r"(c) : "memory")
#define MBAR_ARRIVE(a)  asm volatile("mbarrier.arrive.shared.b64 _, [%0];" :: "r"(a) : "memory")
#define MBAR_EXPECT_TX(a, b) \
    asm volatile("mbarrier.arrive.expect_tx.shared.b64 _, [%0], %1;" :: "r"(a), "r"(b) : "memory")
#define MBAR_WAIT(a, ph)                                                              \
    asm volatile("{\n\t.reg .pred P;\n\t"                                             \
        "WL_%=:\n\t"                                                                  \
        "mbarrier.try_wait.parity.acquire.cta.shared::cta.b64 P, [%0], %1, 0x989680;\n\t" \
        "@P bra.uni WD_%=;\n\t"                                                       \
        "bra.uni WL_%=;\n\t"                                                          \
        "WD_%=:\n\t}" :: "r"(a), "r"(ph) : "memory")

#define LDSM4(R, addr)                                                                \
    asm volatile("ldmatrix.sync.aligned.m8n8.x4.shared.b16 {%0,%1,%2,%3}, [%4];"      \
        : "=r"((R)[0]), "=r"((R)[1]), "=r"((R)[2]), "=r"((R)[3]) : "r"(addr))

__device__ __forceinline__ void mma16(float* d, const uint32_t* a, const uint32_t* b) {
    asm volatile("mma.sync.aligned.m16n8k16.row.col.f32.f16.f16.f32 "
        "{%0,%1,%2,%3}, {%4,%5,%6,%7}, {%8,%9}, {%0,%1,%2,%3};"
        : "+f"(d[0]), "+f"(d[1]), "+f"(d[2]), "+f"(d[3])
        : "r"(a[0]), "r"(a[1]), "r"(a[2]), "r"(a[3]), "r"(b[0]), "r"(b[1]));
}

// ---------------------------------------------------------------------------
__global__ void __launch_bounds__(PTN)
fkan_init(float* __restrict__ out, const float* __restrict__ bias, int n) {
    int t = blockIdx.x * blockDim.x + threadIdx.x;
    if (t < n) out[t] = bias[t & (JD - 1)];
}

// coeffs[d][j][i][k] -> g_B fp16 tiles, SW128-swizzled, k padded to 320.
// One thread per 16B chunk (8 fp16).
__global__ void __launch_bounds__(PTN)
fkan_pre(const float* __restrict__ co) {
    size_t lin = (size_t)blockIdx.x * PTN + threadIdx.x;   // ((i*10+kc)*256+j)*8+c
    if (lin >= (size_t)ID * KCPI * JD * 8) return;
    int c    = (int)(lin & 7);
    int j    = (int)((lin >> 3) & 255);
    int tile = (int)(lin >> 11);
    int kc   = tile % KCPI;
    int i    = tile / KCPI;
    int d    = c >> 2;
    int k0   = kc * 32 + (c & 3) * 8;

    const float* src = co + ((size_t)(d * JD + j) * ID + i) * KG;
    uint32_t hv[4];
    #pragma unroll
    for (int p = 0; p < 4; p++) {
        int ka = k0 + 2 * p, kb = ka + 1;
        float va = (ka < KG) ? src[ka] : 0.f;
        float vb = (kb < KG) ? src[kb] : 0.f;
        hv[p] = pack_h2(va, vb);                 // low half = ka
    }
    uint32_t off = (uint32_t)j * 32 + (((uint32_t)c ^ (uint32_t)(j & 7)) << 2); // uint32 units
    uint4 w = make_uint4(hv[0], hv[1], hv[2], hv[3]);
    *(uint4*)(g_B + (size_t)tile * 8192 + off) = w;
}

// ---------------------------------------------------------------------------
struct PState { float xv, c2, s2; };

// 512 producer threads: thread (r, h, qq) writes chunks h*4+qq*2, +1
// (16 fp16 angles k = kc*32 + qq*16 + {1..16}) of plane h for m-row r.
__device__ __forceinline__ void produce(int u, uint32_t sb, char* smem, int ibase,
                                        const float* xp, int t, int r, int h, int qq,
                                        PState& P)
{
    const int slot = u % 3;
    const int kc   = u % KCPI;
    const int il   = u / KCPI;
    const uint32_t mF = sb + (uint32_t)slot * 8u;

    if (t == 0) {   // B: one 32KB pre-swizzled bulk copy
        const char* src = (const char*)g_B + (size_t)((ibase + il) * KCPI + kc) * 32768;
        MBAR_EXPECT_TX(mF, (uint32_t)B_SZ);
        asm volatile("cp.async.bulk.shared::cluster.global.mbarrier::complete_tx::bytes "
                     "[%0], [%1], %2, [%3];"
                     :: "r"(sb + CTRL + slot * STG + A_SZ), "l"(src),
                        "r"((uint32_t)B_SZ), "r"(mF) : "memory");
    }

    if (kc == 0) { P.xv = xp[il]; __sincosf(P.xv + P.xv, &P.s2, &P.c2); }

    // 16 angles: seeds at k0, k0+1 (fp32 x*k matches reference rounding),
    // both chains rotated by 2x per step.
    const float k0f = (float)(kc * 32 + qq * 16 + 1);
    float s0, c0, s1, c1;
    __sincosf(P.xv * k0f,         &s0, &c0);
    __sincosf(P.xv * (k0f + 1.f), &s1, &c1);

    const int valid = 299 - kc * 32 - qq * 16;   // angle index a kept iff a <= valid
    uint32_t hv[8];
    #pragma unroll
    for (int p = 0; p < 8; p++) {
        float v0 = h ? s0 : c0;                  // a = 2p
        float v1 = h ? s1 : c1;                  // a = 2p+1
        if (2 * p     > valid) v0 = 0.f;
        if (2 * p + 1 > valid) v1 = 0.f;
        hv[p] = pack_h2(v0, v1);
        if (p < 7) {
            float nc0 = c0 * P.c2 - s0 * P.s2, ns0 = s0 * P.c2 + c0 * P.s2;
            float nc1 = c1 * P.c2 - s1 * P.s2, ns1 = s1 * P.c2 + c1 * P.s2;
            c0 = nc0; s0 = ns0; c1 = nc1; s1 = ns1;
        }
    }

    char* Arow = smem + CTRL + slot * STG + r * 128;
    const uint32_t msk = (uint32_t)(r & 7);
    const uint32_t ch = (uint32_t)(h * 4 + qq * 2);
    *(uint4*)(Arow + (((ch)     ^ msk) << 4)) = make_uint4(hv[0], hv[1], hv[2], hv[3]);
    *(uint4*)(Arow + (((ch + 1) ^ msk) << 4)) = make_uint4(hv[4], hv[5], hv[6], hv[7]);
    MBAR_ARRIVE(mF);   // release: A stores visible to full-waiters
}

__global__ void __launch_bounds__(NT, 1)
fkan_gemm(const float* __restrict__ x, float* __restrict__ out)
{
    extern __shared__ char smem[];
    const uint32_t sb = s2u(smem);
    const int t = threadIdx.x, lane = t & 31, wid = t >> 5;
    const int b0    = blockIdx.x * BMT;
    const int ibase = blockIdx.y * I_PER;

    if (t == 0) { MBAR_INIT(sb, NT + 1); MBAR_INIT(sb + 8, NT + 1); MBAR_INIT(sb + 16, NT + 1); }
    __syncthreads();

    // producer ids
    const int r = t & 127, h = (t >> 7) & 1, qq = t >> 8;
    const float* xp = x + (size_t)(b0 + r) * ID + ibase;
    PState P;

    // consumer: 16 warps as 4(m) x 4(n), warp tile 32x64
    const int wm = wid >> 2, wn = wid & 3;
    const int mbase = wm * 32, nbase = wn * 64;
    const uint32_t msk = (uint32_t)(lane & 7);
    const int a_rl = ((lane >> 3) & 1) * 8 + (lane & 7);   // A: lanes 0-15 rows, 16-31 repeat
    const uint32_t akh = (uint32_t)(lane >> 4);            // A k-half chunk
    const int b_rl = ((lane >> 4) << 3) + (lane & 7);      // B: n-row within group
    const uint32_t bkh = (uint32_t)((lane >> 3) & 1);      // B k-half chunk
    uint32_t aoff[2], boff[4];
    #pragma unroll
    for (int mi = 0; mi < 2; mi++) aoff[mi] = (uint32_t)(mbase + mi * 16 + a_rl) * 128u;
    #pragma unroll
    for (int g = 0; g < 4; g++)   boff[g] = (uint32_t)(nbase + g * 16 + b_rl) * 128u;

    float acc[2][8][4];
    #pragma unroll
    for (int a = 0; a < 2; a++)
        #pragma unroll
        for (int b = 0; b < 8; b++)
            #pragma unroll
            for (int c = 0; c < 4; c++) acc[a][b][c] = 0.f;

    produce(0, sb, smem, ibase, xp, t, r, h, qq, P);
    produce(1, sb, smem, ibase, xp, t, r, h, qq, P);
    produce(2, sb, smem, ibase, xp, t, r, h, qq, P);

    for (int s = 0; s < STAGES; s++) {
        const int slot = s % 3;
        const uint32_t ph = (uint32_t)((s / 3) & 1);
        MBAR_WAIT(sb + (uint32_t)slot * 8u, ph);
        const uint32_t Ab = sb + CTRL + slot * STG;
        const uint32_t Bb = Ab + A_SZ;
        #pragma unroll
        for (int kq = 0; kq < 4; kq++) {          // 16 fp16 k per step
            uint32_t av[2][4], bv[4][4];
            const uint32_t ak = ((((uint32_t)(kq * 2) + akh) ^ msk) << 4);
            const uint32_t bk = ((((uint32_t)(kq * 2) + bkh) ^ msk) << 4);
            #pragma unroll
            for (int mi = 0; mi < 2; mi++) LDSM4(av[mi], Ab + aoff[mi] + ak);
            #pragma unroll
            for (int g = 0; g < 4; g++)   LDSM4(bv[g], Bb + boff[g] + bk);
            #pragma unroll
            for (int mi = 0; mi < 2; mi++)
                #pragma unroll
                for (int nt = 0; nt < 8; nt++)
                    mma16(acc[mi][nt], av[mi], &bv[nt >> 1][(nt & 1) * 2]);
        }
        if (s + 3 < STAGES) {
            __syncthreads();                      // all readers done with this slot
            produce(s + 3, sb, smem, ibase, xp, t, r, h, qq, P);
        }
    }

    // epilogue: split-K accumulate (out pre-initialized with bias)
    const int g4 = lane >> 2, t4 = lane & 3;
    #pragma unroll
    for (int mi = 0; mi < 2; mi++) {
        const int row = b0 + mbase + mi * 16 + g4;
        #pragma unroll
        for (int nt = 0; nt < 8; nt++) {
            const int col = nbase + nt * 8 + t4 * 2;
            atomicAdd(out + (size_t)row * JD + col,           acc[mi][nt][0]);
            atomicAdd(out + (size_t)row * JD + col + 1,       acc[mi][nt][1]);
            atomicAdd(out + (size_t)(row + 8) * JD + col,     acc[mi][nt][2]);
            atomicAdd(out + (size_t)(row + 8) * JD + col + 1, acc[mi][nt][3]);
        }
    }
}

// ---------------------------------------------------------------------------
extern "C" void kernel_launch(void* const* d_in, const int* in_sizes, int n_in,
                              void* d_out, int out_size)
{
    const float* x    = (const float*)d_in[0];   // [2048, 256]
    const float* co   = (const float*)d_in[1];   // [2, 256, 256, 300]
    const float* bias = (const float*)d_in[2];   // [1, 256]
    float* out = (float*)d_out;                  // [2048, 256] fp32

    cudaFuncSetAttribute(fkan_gemm, cudaFuncAttributeMaxDynamicSharedMemorySize, SMEM_TOTAL);

    fkan_init<<<(out_size + PTN - 1) / PTN, PTN>>>(out, bias, out_size);
    fkan_pre<<<(int)(((size_t)ID * KCPI * JD * 8 + PTN - 1) / PTN), PTN>>>(co);

    dim3 grid(2048 / BMT, SPLIT);                // (16, 8) = 128 CTAs, one wave
    fkan_gemm<<<grid, NT, SMEM_TOTAL>>>(x, out);
}